// round 16
// baseline (speedup 1.0000x reference)
#include <cuda_runtime.h>
#include <stdint.h>
#include <stddef.h>

// Problem constants (ReinforceDistributed): B=8192, HALL=4096, C=3, EPS=10
#define B_TOT    8192
#define H_ALL    4096
#define N_E      10
#define E_STRIDE 33554432u     // 8192 * 4096 = 2^25
#define TPB      256
#define NEG_BIG  (-3.0e38f)

// Opaque 1: keeps mad.lo.u32 as IMAD (fma pipe) instead of IADD3 (alu pipe).
__device__ uint32_t g_one = 1u;

// Per-row header passed from kernel A (softmax stats) to kernel B (sampling).
struct __align__(16) RowHdr {
    int   best;
    float lp_best, lpmax, lpmin;
    float m0, m1, m2;
    float su0, su1, su2;
    float pad0, pad1;          // 48 bytes
};
__device__ RowHdr g_hdr[B_TOT];

// ---------------------------------------------------------------------------
// JAX threefry2x32, key (0, 42), partitionable path (confirmed R8..R15):
//   bits[i] = out0 ^ out1 of block (c0=0, c1=i)
// ---------------------------------------------------------------------------
static __device__ __forceinline__ uint32_t rotl32(uint32_t x, uint32_t r) {
    return __funnelshift_l(x, x, r);
}

#define ADDF(d, a, b) \
    asm("mad.lo.u32 %0, %1, %2, %3;" : "=r"(d) : "r"(a), "r"(one), "r"(b))

static __device__ __forceinline__ uint32_t tf2x32_xor(uint32_t cnt, uint32_t one) {
    const uint32_t ks1 = 42u;
    const uint32_t ks2 = 0x1BD11BF0u;
    uint32_t x1 = cnt + ks1;
    uint32_t x0 = x1;          // round-1 add folded (0 + x1)
    x1 = rotl32(x1, 13); x1 ^= x0;
#define TFR(r) { ADDF(x0, x0, x1); x1 = rotl32(x1, (r)); x1 ^= x0; }
    TFR(15) TFR(26) TFR(6)
    ADDF(x0, x0, ks1); ADDF(x1, x1, ks2 + 1u);
    TFR(17) TFR(29) TFR(16) TFR(24)
    ADDF(x0, x0, ks2); ADDF(x1, x1, 2u);
    TFR(13) TFR(15) TFR(26) TFR(6)
    ADDF(x1, x1, ks1 + 3u);
    TFR(17) TFR(29) TFR(16) TFR(24)
    ADDF(x0, x0, ks1); ADDF(x1, x1, ks2 + 4u);
    TFR(13) TFR(15) TFR(26) TFR(6)
    ADDF(x0, x0, ks2); ADDF(x1, x1, 5u);
#undef TFR
    return x0 ^ x1;
}

static __device__ __forceinline__ float gumbel_mbits(uint32_t mbits) {
    float f = __uint_as_float(mbits | 0x3f800000u) - 1.0f;
    if (f == 0.0f) f = 1.17549435e-38f;   // float32 tiny
    return -logf(-logf(f));
}

static __device__ __forceinline__ uint32_t fmap(float f) {
    uint32_t u = __float_as_uint(f);
    return (u & 0x80000000u) ? ~u : (u | 0x80000000u);
}
static __device__ __forceinline__ float funmap(uint32_t m) {
    uint32_t u = (m & 0x80000000u) ? (m & 0x7fffffffu) : ~m;
    return __uint_as_float(u);
}

// lenient raw-bits screen threshold: pass iff bits >= returned value.
static __device__ __forceinline__ uint32_t screen_uthr(float T, float lpmax) {
    const float ut = __expf(-__expf(-(T - lpmax)));
    const int thr = (int)(ut * 8388480.0f) - 4;   // 2^23*(1-1.5e-5), -4: lenient
    return (uint32_t)(thr + 1) << 9;
}

static __device__ __forceinline__ void warp_amax(float& v, int& i) {
#pragma unroll
    for (int o = 16; o; o >>= 1) {
        float v2 = __shfl_down_sync(0xffffffffu, v, o);
        int   i2 = __shfl_down_sync(0xffffffffu, i, o);
        if (v2 > v || (v2 == v && i2 < i)) { v = v2; i = i2; }
    }
}

// ===========================================================================
// Kernel A: softmax stats. One CTA per row; register-resident; writes ONLY a
// 48-byte header (no dense p[] -- kernel B re-derives lp(h) from X directly).
// ===========================================================================
__global__ void __launch_bounds__(TPB) rd_a(
    const float* __restrict__ X,     // (8192, 12288)
    const float* __restrict__ W,     // (3, 3)
    const float* __restrict__ Bvec)  // (3,)
{
    __shared__ float s_red[3][8];
    __shared__ float s_max[3];
    __shared__ float s_sum[3];
    __shared__ float s_bv[8];
    __shared__ int   s_bi[8];
    __shared__ float s_pm[8];

    const int b    = blockIdx.x;
    const int tid  = threadIdx.x;
    const int wid  = tid >> 5;
    const int lane = tid & 31;

    const float4* xr4 =
        reinterpret_cast<const float4*>(X + (size_t)b * (H_ALL * 3));

    const float w00 = W[0], w01 = W[1], w02 = W[2];
    const float w10 = W[3], w11 = W[4], w12 = W[5];
    const float w20 = W[6], w21 = W[7], w22 = W[8];
    const float bb0 = Bvec[0], bb1 = Bvec[1], bb2 = Bvec[2];

    // ---- logits into registers; group g = tid + 256j covers h = 4g..4g+3.
    float4 l4[4];
    float lm0 = NEG_BIG, lm1 = NEG_BIG, lm2 = NEG_BIG;
#pragma unroll
    for (int j = 0; j < 4; j++) {
        const int g = tid + j * TPB;
        const float4 a = xr4[3 * g + 0];
        const float4 c = xr4[3 * g + 1];
        const float4 d = xr4[3 * g + 2];
        float ww0, ww1, ww2, bbx;
        if (j < 2)       { ww0 = w00; ww1 = w01; ww2 = w02; bbx = bb0; }
        else if (j == 2) { ww0 = w10; ww1 = w11; ww2 = w12; bbx = bb1; }
        else             { ww0 = w20; ww1 = w21; ww2 = w22; bbx = bb2; }
        l4[j].x = fmaf(a.z, ww2, fmaf(a.y, ww1, a.x * ww0)) + bbx;
        l4[j].y = fmaf(c.y, ww2, fmaf(c.x, ww1, a.w * ww0)) + bbx;
        l4[j].z = fmaf(d.x, ww2, fmaf(c.w, ww1, c.z * ww0)) + bbx;
        l4[j].w = fmaf(d.w, ww2, fmaf(d.z, ww1, d.y * ww0)) + bbx;
        const float lm = fmaxf(fmaxf(l4[j].x, l4[j].y), fmaxf(l4[j].z, l4[j].w));
        if (j < 2)       lm0 = fmaxf(lm0, lm);
        else if (j == 2) lm1 = fmaxf(lm1, lm);
        else             lm2 = fmaxf(lm2, lm);
    }
#pragma unroll
    for (int o = 16; o; o >>= 1) {
        lm0 = fmaxf(lm0, __shfl_xor_sync(0xffffffffu, lm0, o));
        lm1 = fmaxf(lm1, __shfl_xor_sync(0xffffffffu, lm1, o));
        lm2 = fmaxf(lm2, __shfl_xor_sync(0xffffffffu, lm2, o));
    }
    if (!lane) { s_red[0][wid] = lm0; s_red[1][wid] = lm1; s_red[2][wid] = lm2; }
    __syncthreads();
    if (tid < 3) {
        float m = s_red[tid][0];
#pragma unroll
        for (int k = 1; k < 8; k++) m = fmaxf(m, s_red[tid][k]);
        s_max[tid] = m;
    }
    __syncthreads();

    // ---- exp(l - max) in registers; per-split sums
    const float m0 = s_max[0], m1 = s_max[1], m2 = s_max[2];
    float ls0 = 0.f, ls1 = 0.f, ls2 = 0.f;
#pragma unroll
    for (int j = 0; j < 4; j++) {
        const float m = (j < 2) ? m0 : ((j == 2) ? m1 : m2);
        l4[j].x = expf(l4[j].x - m);
        l4[j].y = expf(l4[j].y - m);
        l4[j].z = expf(l4[j].z - m);
        l4[j].w = expf(l4[j].w - m);
        const float t = ((l4[j].x + l4[j].y) + l4[j].z) + l4[j].w;
        if (j < 2) ls0 += t; else if (j == 2) ls1 += t; else ls2 += t;
    }
#pragma unroll
    for (int o = 16; o; o >>= 1) {
        ls0 += __shfl_xor_sync(0xffffffffu, ls0, o);
        ls1 += __shfl_xor_sync(0xffffffffu, ls1, o);
        ls2 += __shfl_xor_sync(0xffffffffu, ls2, o);
    }
    if (!lane) { s_red[0][wid] = ls0; s_red[1][wid] = ls1; s_red[2][wid] = ls2; }
    __syncthreads();
    if (tid < 3) {
        float s = s_red[tid][0];
#pragma unroll
        for (int k = 1; k < 8; k++) s += s_red[tid][k];
        s_sum[tid] = s;
    }
    __syncthreads();

    // ---- p = e/su in registers; argmax p (reference tie-break) + pmin
    const float su0 = s_sum[0], su1 = s_sum[1], su2 = s_sum[2];
    float bv = -1.0f; int bi = 0x7fffffff;
    float pmn = 3.0e38f;
#pragma unroll
    for (int j = 0; j < 4; j++) {
        const float s = (j < 2) ? su0 : ((j == 2) ? su1 : su2);
        const int hb = 4 * (tid + j * TPB);
        float4 p;
        p.x = l4[j].x / s; p.y = l4[j].y / s;
        p.z = l4[j].z / s; p.w = l4[j].w / s;
        if (p.x > bv) { bv = p.x; bi = hb;     }
        if (p.y > bv) { bv = p.y; bi = hb + 1; }
        if (p.z > bv) { bv = p.z; bi = hb + 2; }
        if (p.w > bv) { bv = p.w; bi = hb + 3; }
        pmn = fminf(pmn, fminf(fminf(p.x, p.y), fminf(p.z, p.w)));
    }
    warp_amax(bv, bi);
#pragma unroll
    for (int o = 16; o; o >>= 1)
        pmn = fminf(pmn, __shfl_xor_sync(0xffffffffu, pmn, o));
    if (!lane) { s_bv[wid] = bv; s_bi[wid] = bi; s_pm[wid] = pmn; }
    __syncthreads();
    if (tid == 0) {
        float v = s_bv[0]; int i = s_bi[0]; float pm = s_pm[0];
#pragma unroll
        for (int k = 1; k < 8; k++) {
            if (s_bv[k] > v || (s_bv[k] == v && s_bi[k] < i)) { v = s_bv[k]; i = s_bi[k]; }
            pm = fminf(pm, s_pm[k]);
        }
        RowHdr hd;
        hd.best    = i;
        hd.lp_best = logf(v);                        // logf(p_best), ref path
        hd.lpmax   = fmaxf(fmaxf(-logf(su0), -logf(su1)), -logf(su2)) + 1e-5f;
        hd.lpmin   = logf(pm) - 1e-5f;
        hd.m0 = m0; hd.m1 = m1; hd.m2 = m2;
        hd.su0 = su0; hd.su1 = su1; hd.su2 = su2;
        hd.pad0 = 0.f; hd.pad1 = 0.f;
        g_hdr[b] = hd;
    }
}

// ===========================================================================
// Kernel B: sampling. Recomputes lp(h) at (rare) eval sites from 12 bytes of
// X + header stats -- float path bitwise identical to the reference chain:
//   l = fma(x2,w2,fma(x1,w1,x0*w0))+b ; p = expf(l-m_d)/su_d ; lp = logf(p)
// ===========================================================================
static __device__ __forceinline__ float lp_of(
    const float* __restrict__ xr, int h,
    float w00, float w01, float w02, float w10, float w11, float w12,
    float w20, float w21, float w22, float bb0, float bb1, float bb2,
    float m0, float m1, float m2, float su0, float su1, float su2)
{
    const float x0 = xr[3 * h + 0], x1 = xr[3 * h + 1], x2 = xr[3 * h + 2];
    float ww0, ww1, ww2, bbx, m, su;
    if (h < 2048)      { ww0 = w00; ww1 = w01; ww2 = w02; bbx = bb0; m = m0; su = su0; }
    else if (h < 3072) { ww0 = w10; ww1 = w11; ww2 = w12; bbx = bb1; m = m1; su = su1; }
    else               { ww0 = w20; ww1 = w21; ww2 = w22; bbx = bb2; m = m2; su = su2; }
    const float l = fmaf(x2, ww2, fmaf(x1, ww1, x0 * ww0)) + bbx;
    return logf(expf(l - m) / su);
}

__global__ void __launch_bounds__(TPB) rd_b(
    const float* __restrict__ X,     // (8192, 12288)
    const float* __restrict__ W,     // (3, 3)
    const float* __restrict__ Bvec,  // (3,)
    float* __restrict__ out)         // (8192,) float32
{
    __shared__ int   s_alive[9];
    __shared__ float s_T[9];
    __shared__ uint32_t s_uthr[9];
    __shared__ float s_w9v[8];
    __shared__ int   s_w9i[8];

    const int b    = blockIdx.x;
    const int tid  = threadIdx.x;
    const int wid  = tid >> 5;
    const int lane = tid & 31;

    const uint32_t one = *(volatile uint32_t*)&g_one;

    const float* xr = X + (size_t)b * (H_ALL * 3);
    const RowHdr hd = g_hdr[b];

    const float w00 = W[0], w01 = W[1], w02 = W[2];
    const float w10 = W[3], w11 = W[4], w12 = W[5];
    const float w20 = W[6], w21 = W[7], w22 = W[8];
    const float bb0 = Bvec[0], bb1 = Bvec[1], bb2 = Bvec[2];

#define LP_OF(h) lp_of(xr, (h), w00, w01, w02, w10, w11, w12, w20, w21, w22, \
                       bb0, bb1, bb2, hd.m0, hd.m1, hd.m2, hd.su0, hd.su1, hd.su2)

    const int best = hd.best;
    const uint32_t cbase = ((uint32_t)b << 12);

    if (tid < 9) {
        s_alive[tid] = 1;
        const uint32_t mb =
            tf2x32_xor(cbase + (uint32_t)best + (uint32_t)tid * E_STRIDE, one) >> 9;
        const float T = gumbel_mbits(mb) + hd.lp_best;
        s_T[tid]    = T;
        s_uthr[tid] = screen_uthr(T, hd.lpmax);
    }
    __syncthreads();

    // ---- warp-specialized early-kill scans for draws 0..8
    for (int e = wid; e < 9; e += 8) {
        const float T  = s_T[e];
        const uint32_t uth = s_uthr[e];
        const uint32_t ce = cbase + (uint32_t)e * E_STRIDE;
        bool killed = false;
#pragma unroll 1
        for (int k = 0; k < H_ALL / 32 && !killed; k++) {
            const int h = lane + k * 32;
            const uint32_t bits = tf2x32_xor(ce + (uint32_t)h, one);
            bool kill = false;
            if (bits >= uth) {                              // lenient screen
                const float v = gumbel_mbits(bits >> 9) + LP_OF(h);
                kill = (v > T) || (v == T && h < best);     // exact verify
            }
            killed = (__ballot_sync(0xffffffffu, kill) != 0u);
        }
        if (killed && lane == 0) s_alive[e] = 0;
    }

    // ---- draw 9: screened running argmax (samples[-1]), ILP2, peeled iter 0
    float mv9 = NEG_BIG; int mi9 = 0;
    const uint32_t c9 = cbase + 9u * E_STRIDE;
    uint32_t uthr9;
    {
        const uint32_t bits0 = tf2x32_xor(c9 + (uint32_t)tid, one);
        const uint32_t bits1 = tf2x32_xor(c9 + (uint32_t)(tid + 256), one);
        const uint32_t wm = __reduce_max_sync(0xffffffffu,
                                              bits0 > bits1 ? bits0 : bits1);
        uthr9 = screen_uthr(gumbel_mbits(wm >> 9) + hd.lpmin, hd.lpmax);
        if (bits0 >= uthr9) {
            const float v = gumbel_mbits(bits0 >> 9) + LP_OF(tid);
            if (v > mv9) { mv9 = v; mi9 = tid; }
        }
        if (bits1 >= uthr9) {
            const float v = gumbel_mbits(bits1 >> 9) + LP_OF(tid + 256);
            if (v > mv9) { mv9 = v; mi9 = tid + 256; }
        }
    }
#pragma unroll 1
    for (int j = 1; j < 8; j++) {
        const int h0 = tid + j * 512;
        const int h1 = h0 + 256;
        const uint32_t bits0 = tf2x32_xor(c9 + (uint32_t)h0, one);
        const uint32_t bits1 = tf2x32_xor(c9 + (uint32_t)h1, one);
        if (bits0 >= uthr9) {
            const float v = gumbel_mbits(bits0 >> 9) + LP_OF(h0);
            if (v > mv9) { mv9 = v; mi9 = h0; }
        }
        if (bits1 >= uthr9) {
            const float v = gumbel_mbits(bits1 >> 9) + LP_OF(h1);
            if (v > mv9) { mv9 = v; mi9 = h1; }
        }
        if (j == 1 || j == 3) {                             // sparse refresh
            const uint32_t wm = __reduce_max_sync(0xffffffffu, fmap(mv9));
            const uint32_t nt = screen_uthr(funmap(wm), hd.lpmax);
            uthr9 = nt > uthr9 ? nt : uthr9;                // never loosen
        }
    }
#undef LP_OF

    // ---- block argmax for draw 9, then output
    warp_amax(mv9, mi9);
    if (!lane) { s_w9v[wid] = mv9; s_w9i[wid] = mi9; }
    __syncthreads();
    if (tid == 0) {
        float v = s_w9v[0]; int a9 = s_w9i[0];
#pragma unroll
        for (int k = 1; k < 8; k++) {
            if (s_w9v[k] > v || (s_w9v[k] == v && s_w9i[k] < a9)) { v = s_w9v[k]; a9 = s_w9i[k]; }
        }
        bool hit = (a9 == best);
#pragma unroll
        for (int e = 0; e < 9; e++) hit = hit || (s_alive[e] != 0);
        out[b] = (float)(hit ? best : a9);
    }
}

extern "C" void kernel_launch(void* const* d_in, const int* in_sizes, int n_in,
                              void* d_out, int out_size) {
    (void)in_sizes; (void)n_in; (void)out_size;
    const float* X = (const float*)d_in[0];
    const float* W = (const float*)d_in[1];
    const float* b = (const float*)d_in[2];
    rd_a<<<B_TOT, TPB>>>(X, W, b);
    rd_b<<<B_TOT, TPB>>>(X, W, b, (float*)d_out);
}

// round 17
// speedup vs baseline: 1.3417x; 1.3417x over previous
#include <cuda_runtime.h>
#include <stdint.h>
#include <stddef.h>

// Problem constants (ReinforceDistributed): B=8192, HALL=4096, C=3, EPS=10
#define B_TOT    8192
#define H_ALL    4096
#define N_E      10
#define E_STRIDE 33554432u     // 8192 * 4096 = 2^25
#define TPB      256
#define NEG_BIG  (-3.0e38f)

// Opaque 1: keeps mad.lo.u32 as IMAD (fma pipe) instead of IADD3 (alu pipe).
__device__ uint32_t g_one = 1u;

// ---------------------------------------------------------------------------
// JAX threefry2x32, key (0, 42), partitionable path (confirmed R8..R16):
//   bits[i] = out0 ^ out1 of block (c0=0, c1=i)
// ---------------------------------------------------------------------------
static __device__ __forceinline__ uint32_t rotl32(uint32_t x, uint32_t r) {
    return __funnelshift_l(x, x, r);
}

#define ADDF(d, a, b) \
    asm("mad.lo.u32 %0, %1, %2, %3;" : "=r"(d) : "r"(a), "r"(one), "r"(b))

static __device__ __forceinline__ uint32_t tf2x32_xor(uint32_t cnt, uint32_t one) {
    const uint32_t ks1 = 42u;
    const uint32_t ks2 = 0x1BD11BF0u;
    uint32_t x1 = cnt + ks1;
    uint32_t x0 = x1;          // round-1 add folded (0 + x1)
    x1 = rotl32(x1, 13); x1 ^= x0;
#define TFR(r) { ADDF(x0, x0, x1); x1 = rotl32(x1, (r)); x1 ^= x0; }
    TFR(15) TFR(26) TFR(6)
    ADDF(x0, x0, ks1); ADDF(x1, x1, ks2 + 1u);
    TFR(17) TFR(29) TFR(16) TFR(24)
    ADDF(x0, x0, ks2); ADDF(x1, x1, 2u);
    TFR(13) TFR(15) TFR(26) TFR(6)
    ADDF(x1, x1, ks1 + 3u);
    TFR(17) TFR(29) TFR(16) TFR(24)
    ADDF(x0, x0, ks1); ADDF(x1, x1, ks2 + 4u);
    TFR(13) TFR(15) TFR(26) TFR(6)
    ADDF(x0, x0, ks2); ADDF(x1, x1, 5u);
#undef TFR
    return x0 ^ x1;
}

// uniform f from mantissa bits (bits>>9), matching JAX bit-for-bit
static __device__ __forceinline__ float f_of(uint32_t mbits) {
    float f = __uint_as_float(mbits | 0x3f800000u) - 1.0f;
    if (f == 0.0f) f = 1.17549435e-38f;   // float32 tiny
    return f;
}

// Lenient raw-bits screen from a ratio bound r (candidate needs y <= r*p):
// pass iff f >= exp(-r*pmx). Margins: x(1-3.7e-5), -8 counts, clamp >= -1
// (clamp fixes pass-none wraparound when ut underflows to 0).
static __device__ __forceinline__ uint32_t screen_uthr_r(float r, float pmx) {
    const float ut = __expf(-r * pmx);
    int thr = (int)(ut * 8388300.0f) - 8;
    if (thr < -1) thr = -1;
    return (uint32_t)(thr + 1) << 9;
}

// ---------------------------------------------------------------------------
// One CTA per batch row b.
// Phase A: float4 logits -> register softmax -> p[] in SMEM; best = argmax p.
// Phase B in RATIO space: v = g + logp is maximized <=> r = y/p minimized,
//   y = -logf(u). All compares are cross-multiplied (y1*p2 < y2*p1): one logf
//   per eval site, no gumbel double-log, no logp.
//   draws 0..8: warp-specialized early-kill scans vs best's own ratio r_e;
//   draw 9:     screened running argmin of y/p (samples[-1]).
// ---------------------------------------------------------------------------
__global__ void __launch_bounds__(TPB) rd_kernel(
    const float* __restrict__ X,     // (8192, 12288)
    const float* __restrict__ W,     // (3, 3)
    const float* __restrict__ Bvec,  // (3,)
    float* __restrict__ out)         // (8192,) float32
{
    __shared__ float sh[H_ALL];            // softmax probs p
    __shared__ float s_red[3][8];
    __shared__ float s_max[3];
    __shared__ float s_sum[3];
    __shared__ float s_bv[8];
    __shared__ int   s_bi[8];
    __shared__ float s_pm[8];
    __shared__ int   s_best;
    __shared__ float s_pbest, s_pmx, s_pmn;
    __shared__ int   s_alive[9];
    __shared__ float s_ye[9];              // y of best's draw e (ratio numerator)
    __shared__ uint32_t s_uthr[9];
    __shared__ float s_w9y[8], s_w9p[8];
    __shared__ int   s_w9i[8];

    const int b    = blockIdx.x;
    const int tid  = threadIdx.x;
    const int wid  = tid >> 5;
    const int lane = tid & 31;

    const uint32_t one = *(volatile uint32_t*)&g_one;

    const float4* xr4 =
        reinterpret_cast<const float4*>(X + (size_t)b * (H_ALL * 3));
    float4* sh4 = reinterpret_cast<float4*>(sh);

    const float w00 = W[0], w01 = W[1], w02 = W[2];
    const float w10 = W[3], w11 = W[4], w12 = W[5];
    const float w20 = W[6], w21 = W[7], w22 = W[8];
    const float bb0 = Bvec[0], bb1 = Bvec[1], bb2 = Bvec[2];

    // ---- logits into registers; g = tid + 256j covers h = 4g..4g+3.
    float4 l4[4];
    float lm0 = NEG_BIG, lm1 = NEG_BIG, lm2 = NEG_BIG;
#pragma unroll
    for (int j = 0; j < 4; j++) {
        const int g = tid + j * TPB;
        const float4 a = xr4[3 * g + 0];
        const float4 c = xr4[3 * g + 1];
        const float4 d = xr4[3 * g + 2];
        float ww0, ww1, ww2, bbx;
        if (j < 2)       { ww0 = w00; ww1 = w01; ww2 = w02; bbx = bb0; }
        else if (j == 2) { ww0 = w10; ww1 = w11; ww2 = w12; bbx = bb1; }
        else             { ww0 = w20; ww1 = w21; ww2 = w22; bbx = bb2; }
        l4[j].x = fmaf(a.z, ww2, fmaf(a.y, ww1, a.x * ww0)) + bbx;
        l4[j].y = fmaf(c.y, ww2, fmaf(c.x, ww1, a.w * ww0)) + bbx;
        l4[j].z = fmaf(d.x, ww2, fmaf(c.w, ww1, c.z * ww0)) + bbx;
        l4[j].w = fmaf(d.w, ww2, fmaf(d.z, ww1, d.y * ww0)) + bbx;
        const float lm = fmaxf(fmaxf(l4[j].x, l4[j].y), fmaxf(l4[j].z, l4[j].w));
        if (j < 2)       lm0 = fmaxf(lm0, lm);
        else if (j == 2) lm1 = fmaxf(lm1, lm);
        else             lm2 = fmaxf(lm2, lm);
    }
#pragma unroll
    for (int o = 16; o; o >>= 1) {
        lm0 = fmaxf(lm0, __shfl_xor_sync(0xffffffffu, lm0, o));
        lm1 = fmaxf(lm1, __shfl_xor_sync(0xffffffffu, lm1, o));
        lm2 = fmaxf(lm2, __shfl_xor_sync(0xffffffffu, lm2, o));
    }
    if (!lane) { s_red[0][wid] = lm0; s_red[1][wid] = lm1; s_red[2][wid] = lm2; }
    __syncthreads();
    if (tid < 3) {
        float m = s_red[tid][0];
#pragma unroll
        for (int k = 1; k < 8; k++) m = fmaxf(m, s_red[tid][k]);
        s_max[tid] = m;
    }
    __syncthreads();

    // ---- exp(l - max) in registers; per-split sums
    const float m0 = s_max[0], m1 = s_max[1], m2 = s_max[2];
    float ls0 = 0.f, ls1 = 0.f, ls2 = 0.f;
#pragma unroll
    for (int j = 0; j < 4; j++) {
        const float m = (j < 2) ? m0 : ((j == 2) ? m1 : m2);
        l4[j].x = expf(l4[j].x - m);
        l4[j].y = expf(l4[j].y - m);
        l4[j].z = expf(l4[j].z - m);
        l4[j].w = expf(l4[j].w - m);
        const float t = ((l4[j].x + l4[j].y) + l4[j].z) + l4[j].w;
        if (j < 2) ls0 += t; else if (j == 2) ls1 += t; else ls2 += t;
    }
#pragma unroll
    for (int o = 16; o; o >>= 1) {
        ls0 += __shfl_xor_sync(0xffffffffu, ls0, o);
        ls1 += __shfl_xor_sync(0xffffffffu, ls1, o);
        ls2 += __shfl_xor_sync(0xffffffffu, ls2, o);
    }
    if (!lane) { s_red[0][wid] = ls0; s_red[1][wid] = ls1; s_red[2][wid] = ls2; }
    __syncthreads();
    if (tid < 3) {
        float s = s_red[tid][0];
#pragma unroll
        for (int k = 1; k < 8; k++) s += s_red[tid][k];
        s_sum[tid] = s;
    }
    __syncthreads();

    // ---- p = e/su into SMEM; argmax p (first-index ties) + min p
    const float su0 = s_sum[0], su1 = s_sum[1], su2 = s_sum[2];
    float bv = -1.0f; int bi = 0x7fffffff;
    float pmn = 3.0e38f;
#pragma unroll
    for (int j = 0; j < 4; j++) {
        const float s = (j < 2) ? su0 : ((j == 2) ? su1 : su2);
        const int g = tid + j * TPB;
        const int hb = 4 * g;
        float4 p;
        p.x = l4[j].x / s; p.y = l4[j].y / s;
        p.z = l4[j].z / s; p.w = l4[j].w / s;
        if (p.x > bv) { bv = p.x; bi = hb;     }
        if (p.y > bv) { bv = p.y; bi = hb + 1; }
        if (p.z > bv) { bv = p.z; bi = hb + 2; }
        if (p.w > bv) { bv = p.w; bi = hb + 3; }
        pmn = fminf(pmn, fminf(fminf(p.x, p.y), fminf(p.z, p.w)));
        sh4[g] = p;
    }
#pragma unroll
    for (int o = 16; o; o >>= 1) {
        float v2 = __shfl_down_sync(0xffffffffu, bv, o);
        int   i2 = __shfl_down_sync(0xffffffffu, bi, o);
        if (v2 > bv || (v2 == bv && i2 < bi)) { bv = v2; bi = i2; }
        pmn = fminf(pmn, __shfl_xor_sync(0xffffffffu, pmn, o));
    }
    if (!lane) { s_bv[wid] = bv; s_bi[wid] = bi; s_pm[wid] = pmn; }
    if (tid < 9) s_alive[tid] = 1;
    __syncthreads();
    if (tid == 0) {
        float v = s_bv[0]; int i = s_bi[0]; float pm = s_pm[0];
#pragma unroll
        for (int k = 1; k < 8; k++) {
            if (s_bv[k] > v || (s_bv[k] == v && s_bi[k] < i)) { v = s_bv[k]; i = s_bi[k]; }
            pm = fminf(pm, s_pm[k]);
        }
        s_best  = i;
        s_pbest = v;
        // pmx >= max p (e <= 1 so p <= 1/su), pmn <= min p, with fp margins
        const float px = fmaxf(fmaxf(1.0f / su0, 1.0f / su1), 1.0f / su2);
        s_pmx = px * (1.0f + 3e-5f);
        s_pmn = pm * (1.0f - 3e-5f);
    }
    __syncthreads();
    const int   best  = s_best;
    const float pbest = s_pbest;
    const float pmx   = s_pmx;
    const float pmn_m = s_pmn;
    const uint32_t cbase = ((uint32_t)b << 12);

    // ---- best's own draw value per e (ratio r_e = y_e / pbest) + kill screens
    if (tid < 9) {
        const uint32_t mb =
            tf2x32_xor(cbase + (uint32_t)best + (uint32_t)tid * E_STRIDE, one) >> 9;
        const float ye = -logf(f_of(mb));
        s_ye[tid]   = ye;
        s_uthr[tid] = screen_uthr_r(ye / pbest, pmx);
    }
    __syncthreads();

    // ---- warp-specialized early-kill scans for draws 0..8
    // kill at h: y(h)/p(h) < ye/pbest  <=>  y(h)*pbest < ye*p(h) (ties: h<best)
    for (int e = wid; e < 9; e += 8) {
        const float ye = s_ye[e];
        const uint32_t uth = s_uthr[e];
        const uint32_t ce = cbase + (uint32_t)e * E_STRIDE;
        bool killed = false;
#pragma unroll 1
        for (int k = 0; k < H_ALL / 32 && !killed; k++) {
            const int h = lane + k * 32;
            const uint32_t bits = tf2x32_xor(ce + (uint32_t)h, one);
            bool kill = false;
            if (bits >= uth) {
                const float y = -logf(f_of(bits >> 9));
                const float lhs = y * pbest, rhs = ye * sh[h];
                kill = (lhs < rhs) || (lhs == rhs && h < best);
            }
            killed = (__ballot_sync(0xffffffffu, kill) != 0u);
        }
        if (killed && lane == 0) s_alive[e] = 0;
    }

    // ---- draw 9: screened running ARGMIN of y/p (pair-tracked, no division)
    float ystar = 3.0e38f, pstar = 1.0f; int mi9 = 0;
    const uint32_t c9 = cbase + 9u * E_STRIDE;
    uint32_t uthr9;
    {   // peeled iter 0 with seeded screen: the h achieving warp-max bits has
        // ratio <= y(wm)/pmn_m -> true upper bound on the final min ratio
        const uint32_t bits0 = tf2x32_xor(c9 + (uint32_t)tid, one);
        const uint32_t bits1 = tf2x32_xor(c9 + (uint32_t)(tid + 256), one);
        const uint32_t wm = __reduce_max_sync(0xffffffffu,
                                              bits0 > bits1 ? bits0 : bits1);
        const float ywm = -logf(f_of(wm >> 9));
        uthr9 = screen_uthr_r(ywm / pmn_m, pmx);
        if (bits0 >= uthr9) {
            const float y = -logf(f_of(bits0 >> 9));
            const float p = sh[tid];
            if (y * pstar < ystar * p) { ystar = y; pstar = p; mi9 = tid; }
        }
        if (bits1 >= uthr9) {
            const float y = -logf(f_of(bits1 >> 9));
            const float p = sh[tid + 256];
            if (y * pstar < ystar * p) { ystar = y; pstar = p; mi9 = tid + 256; }
        }
    }
#pragma unroll 1
    for (int j = 1; j < 8; j++) {
        const int h0 = tid + j * 512;
        const int h1 = h0 + 256;
        const uint32_t bits0 = tf2x32_xor(c9 + (uint32_t)h0, one);
        const uint32_t bits1 = tf2x32_xor(c9 + (uint32_t)h1, one);
        if (bits0 >= uthr9) {
            const float y = -logf(f_of(bits0 >> 9));
            const float p = sh[h0];
            if (y * pstar < ystar * p) { ystar = y; pstar = p; mi9 = h0; }
        }
        if (bits1 >= uthr9) {
            const float y = -logf(f_of(bits1 >> 9));
            const float p = sh[h1];
            if (y * pstar < ystar * p) { ystar = y; pstar = p; mi9 = h1; }
        }
        if (j == 1 || j == 3) {       // sparse refresh from warp-min ratio
            // positive floats order as uints; reduce on ratio bits
            const float rcur = ystar / pstar;
            const uint32_t wr = __reduce_min_sync(0xffffffffu,
                                                  __float_as_uint(rcur));
            const uint32_t nt = screen_uthr_r(__uint_as_float(wr), pmx);
            uthr9 = nt > uthr9 ? nt : uthr9;               // never loosen
        }
    }

    // ---- block argmin for draw 9 (cross-multiplied compares), then output
#pragma unroll
    for (int o = 16; o; o >>= 1) {
        const float y2 = __shfl_down_sync(0xffffffffu, ystar, o);
        const float p2 = __shfl_down_sync(0xffffffffu, pstar, o);
        const int   i2 = __shfl_down_sync(0xffffffffu, mi9,   o);
        const float lhs = y2 * pstar, rhs = ystar * p2;
        if (lhs < rhs || (lhs == rhs && i2 < mi9)) { ystar = y2; pstar = p2; mi9 = i2; }
    }
    if (!lane) { s_w9y[wid] = ystar; s_w9p[wid] = pstar; s_w9i[wid] = mi9; }
    __syncthreads();
    if (tid == 0) {
        float yb = s_w9y[0], pb = s_w9p[0]; int a9 = s_w9i[0];
#pragma unroll
        for (int k = 1; k < 8; k++) {
            const float lhs = s_w9y[k] * pb, rhs = yb * s_w9p[k];
            if (lhs < rhs || (lhs == rhs && s_w9i[k] < a9)) {
                yb = s_w9y[k]; pb = s_w9p[k]; a9 = s_w9i[k];
            }
        }
        bool hit = (a9 == best);
#pragma unroll
        for (int e = 0; e < 9; e++) hit = hit || (s_alive[e] != 0);
        out[b] = (float)(hit ? best : a9);
    }
}

extern "C" void kernel_launch(void* const* d_in, const int* in_sizes, int n_in,
                              void* d_out, int out_size) {
    (void)in_sizes; (void)n_in; (void)out_size;
    const float* X = (const float*)d_in[0];
    const float* W = (const float*)d_in[1];
    const float* b = (const float*)d_in[2];
    rd_kernel<<<B_TOT, TPB>>>(X, W, b, (float*)d_out);
}